// round 4
// baseline (speedup 1.0000x reference)
#include <cuda_runtime.h>
#include <math.h>
#include <stdint.h>

#define T_   4096
#define H_   2048
#define E_   32
#define KTOP 4
#define I_   1408
#define R_   128
#define SI_  2816
#define TK_  (T_*KTOP)

// ---------------- scratch (device globals; no allocation allowed) ----------------
__device__ __align__(16) int   g_cnt[E_];
__device__ __align__(16) int   g_off[E_+1];
__device__ __align__(16) int   g_tok2d[E_*T_];
__device__ __align__(16) float g_w2d[E_*T_];
__device__ __align__(16) int   g_tokslot[TK_];
__device__ __align__(16) float g_wslot[TK_];
__device__ __align__(16) int   g_slot_of[TK_];
__device__ __align__(16) int   g_tokc[T_];

__device__ __align__(16) float g_projW[4*R_*H_];   // packed Rg,Ru,s_Rg,s_Ru
__device__ __align__(16) float g_sUW[2*R_*R_];     // packed s_Ug,s_Uu
__device__ __align__(16) float g_proj[4*(size_t)T_*R_]; // rg, ru, srg, sru planes
__device__ __align__(16) float g_st[2*(size_t)T_*R_];   // st1, st2 planes

__device__ __align__(16) float g_tg[TK_*R_];
__device__ __align__(16) float g_tu[TK_*R_];
__device__ __align__(16) float g_h[(size_t)TK_*I_];
__device__ __align__(16) float g_rd[TK_*R_];
__device__ __align__(16) float g_td[TK_*R_];
__device__ __align__(16) float g_sh[(size_t)T_*SI_];
__device__ __align__(16) float g_srd[T_*R_];
__device__ __align__(16) float g_std[T_*R_];
__device__ __align__(16) float g_eout[(size_t)TK_*H_];
__device__ __align__(16) float g_split[2*(size_t)TK_*R_];  // split-K partial planes

// ---------------- init ----------------
__global__ void init_kernel() {
    int i = blockIdx.x*256 + threadIdx.x;
    if (i < E_) g_cnt[i] = 0;
    if (i < T_) g_tokc[i] = 0;
}

// ---------------- gate: fp32 logits, softmax, top-4 (fp32: routing-critical) ----------------
__global__ void gate_kernel(const float* __restrict__ x, const float* __restrict__ gw) {
    __shared__ float xs[H_];
    __shared__ float lg[E_];
    int t = blockIdx.x;
    const float* xr = x + (size_t)t*H_;
    for (int i = threadIdx.x; i < H_; i += 256) xs[i] = xr[i];
    __syncthreads();
    int warp = threadIdx.x >> 5, lane = threadIdx.x & 31;
    for (int e = warp; e < E_; e += 8) {
        const float* w = gw + (size_t)e*H_;
        float s = 0.f;
        for (int i = lane; i < H_; i += 32) s += xs[i]*w[i];
        #pragma unroll
        for (int o = 16; o; o >>= 1) s += __shfl_xor_sync(0xffffffffu, s, o);
        if (lane == 0) lg[e] = s;
    }
    __syncthreads();
    if (threadIdx.x == 0) {
        float mx = lg[0];
        for (int e = 1; e < E_; e++) mx = fmaxf(mx, lg[e]);
        float p[E_]; float sum = 0.f;
        for (int e = 0; e < E_; e++) { p[e] = expf(lg[e]-mx); sum += p[e]; }
        float inv = 1.f/sum;
        bool taken[E_];
        for (int e = 0; e < E_; e++) taken[e] = false;
        int idx[KTOP]; float w4[KTOP]; float ws = 0.f;
        for (int k = 0; k < KTOP; k++) {
            int best = 0; float bv = -1.f;
            for (int e = 0; e < E_; e++)
                if (!taken[e] && p[e] > bv) { bv = p[e]; best = e; }
            taken[best] = true; idx[k] = best; w4[k] = bv*inv; ws += w4[k];
        }
        float rn = 1.f/(ws + 1e-20f);
        for (int k = 0; k < KTOP; k++) {
            int e = idx[k];
            int pos = atomicAdd(&g_cnt[e], 1);
            g_tok2d[e*T_ + pos] = t;
            g_w2d [e*T_ + pos] = w4[k]*rn;
        }
    }
}

__global__ void scan_kernel() {
    if (threadIdx.x == 0 && blockIdx.x == 0) {
        int a = 0;
        for (int e = 0; e < E_; e++) { g_off[e] = a; a += g_cnt[e]; }
        g_off[E_] = a;
    }
}

__global__ void compact_kernel() {
    int e = blockIdx.y;
    int i = blockIdx.x*256 + threadIdx.x;
    if (i < g_cnt[e]) {
        int slot = g_off[e] + i;
        int tok = g_tok2d[e*T_ + i];
        g_tokslot[slot] = tok;
        g_wslot[slot]   = g_w2d[e*T_ + i];
        int c = atomicAdd(&g_tokc[tok], 1);
        g_slot_of[tok*KTOP + c] = slot;
    }
}

// ---------------- 3xTF32 tensor-core TN GEMM, cp.async double-buffered ----------------
// C[M,N] = epi(A[M,K] @ W[N,K]^T)
// EPI: 0 store, 1 silu, 2 C*=res, 3 rowscale*res
// ZMODE: 0 = expert (off[] row ranges, W+z*wstride)
//        1 = dense multi (A+z*astride, W+z*wstride, C+z*cstride)
//        2 = split-K (k range z*Kd.., C plane z*cstride)
// Tile 128x128x32, 8 warps (4m x 2n), warp 32x64 via m16n8k8; 3 MMAs/frag-pair.

__device__ __forceinline__ uint32_t f2tf32(float f) {
    uint32_t r; asm("cvt.rna.tf32.f32 %0, %1;" : "=r"(r) : "f"(f)); return r;
}
__device__ __forceinline__ void tsplit(float f, uint32_t& h, uint32_t& l) {
    h = f2tf32(f);
    l = f2tf32(f - __uint_as_float(h));
}
__device__ __forceinline__ void mma_tf32(float* d, const uint32_t* a, const uint32_t* b) {
    asm volatile(
        "mma.sync.aligned.m16n8k8.row.col.f32.tf32.tf32.f32 "
        "{%0,%1,%2,%3},{%4,%5,%6,%7},{%8,%9},{%0,%1,%2,%3};\n"
        : "+f"(d[0]), "+f"(d[1]), "+f"(d[2]), "+f"(d[3])
        : "r"(a[0]), "r"(a[1]), "r"(a[2]), "r"(a[3]), "r"(b[0]), "r"(b[1]));
}
__device__ __forceinline__ void cpa16(float* dst, const float* src, bool v) {
    uint32_t d = (uint32_t)__cvta_generic_to_shared(dst);
    int sz = v ? 16 : 0;
    asm volatile("cp.async.cg.shared.global [%0], [%1], 16, %2;\n" :: "r"(d), "l"(src), "r"(sz));
}
__device__ __forceinline__ float epi_silu(float v) { return v / (1.f + expf(-v)); }

#define LDSA 36   // bank = (4g+t) mod 32 -> conflict-free fragment loads
#define GSMEM (2*2*128*LDSA*4)

template<int EPI, int ZMODE>
__global__ __launch_bounds__(256)
void gemm3(const float* __restrict__ A, int lda, size_t astride,
           const float* __restrict__ W, size_t wstride, int ldw,
           float* __restrict__ C, int ldc, size_t cstride,
           int M, int N, int Kd,
           const int* __restrict__ off,
           const int* __restrict__ rowmap,
           const float* __restrict__ rowscale)
{
    int z = blockIdx.z;
    int rs = 0, re = M, k_base = 0;
    const float* Ab = A; const float* Wb = W; float* Cb = C;
    if (ZMODE == 0) { rs = off[z]; re = off[z+1]; Wb = W + (size_t)z*wstride; }
    else if (ZMODE == 1) { Ab = A + (size_t)z*astride; Wb = W + (size_t)z*wstride; Cb = C + (size_t)z*cstride; }
    else { k_base = z*Kd; Cb = C + (size_t)z*cstride; }

    int row0 = rs + blockIdx.x * 128;
    if (row0 >= re) return;
    int col0 = blockIdx.y * 128;

    extern __shared__ float sm[];
    float* AsB = sm;                     // [2][128][LDSA]
    float* BsB = sm + 2*128*LDSA;
    #define AS(s,m,k) AsB[(s)*(128*LDSA) + (m)*LDSA + (k)]
    #define BS(s,n,k) BsB[(s)*(128*LDSA) + (n)*LDSA + (k)]

    int tid  = threadIdx.x;
    int wid  = tid >> 5, lane = tid & 31;
    int g    = lane >> 2, t = lane & 3;
    int wm   = wid & 3;
    int wn   = wid >> 2;

    float acc[2][8][4];
    #pragma unroll
    for (int a0 = 0; a0 < 2; a0++)
        #pragma unroll
        for (int b0 = 0; b0 < 8; b0++)
            #pragma unroll
            for (int c0 = 0; c0 < 4; c0++) acc[a0][b0][c0] = 0.f;

    int iters = Kd / 32;

    // stage loader
    auto stage = [&](int s, int k0) {
        #pragma unroll
        for (int it = 0; it < 4; it++) {
            int pos = tid + it*256;
            int m = pos >> 3, kq = (pos & 7) * 4;
            int r = row0 + m;
            bool v = (r < re);
            int ar = v ? ((ZMODE == 0 && rowmap) ? rowmap[r] : r) : 0;
            cpa16(&AS(s, m, kq), Ab + (size_t)ar*lda + k_base + k0 + kq, v);
        }
        #pragma unroll
        for (int it = 0; it < 4; it++) {
            int pos = tid + it*256;
            int n = pos >> 3, kq = (pos & 7) * 4;
            cpa16(&BS(s, n, kq), Wb + (size_t)(col0 + n)*ldw + k_base + k0 + kq, true);
        }
    };

    stage(0, 0);
    asm volatile("cp.async.commit_group;\n");

    for (int kt = 0; kt < iters; kt++) {
        if (kt + 1 < iters) stage((kt+1) & 1, (kt+1)*32);
        asm volatile("cp.async.commit_group;\n");
        asm volatile("cp.async.wait_group 1;\n");
        __syncthreads();
        int s = kt & 1;

        #pragma unroll
        for (int kk = 0; kk < 32; kk += 8) {
            uint32_t bh[8][2], bl[8][2];
            #pragma unroll
            for (int nt = 0; nt < 8; nt++) {
                int nb = wn*64 + nt*8 + g;
                tsplit(BS(s, nb, kk + t),     bh[nt][0], bl[nt][0]);
                tsplit(BS(s, nb, kk + t + 4), bh[nt][1], bl[nt][1]);
            }
            #pragma unroll
            for (int mt = 0; mt < 2; mt++) {
                int mb = wm*32 + mt*16;
                uint32_t ah[4], al[4];
                tsplit(AS(s, mb + g,     kk + t),     ah[0], al[0]);
                tsplit(AS(s, mb + g + 8, kk + t),     ah[1], al[1]);
                tsplit(AS(s, mb + g,     kk + t + 4), ah[2], al[2]);
                tsplit(AS(s, mb + g + 8, kk + t + 4), ah[3], al[3]);
                #pragma unroll
                for (int nt = 0; nt < 8; nt++) {
                    mma_tf32(acc[mt][nt], al, bh[nt]);   // lo x hi
                    mma_tf32(acc[mt][nt], ah, bl[nt]);   // hi x lo
                    mma_tf32(acc[mt][nt], ah, bh[nt]);   // hi x hi last
                }
            }
        }
        __syncthreads();
    }

    #pragma unroll
    for (int mt = 0; mt < 2; mt++) {
        #pragma unroll
        for (int half = 0; half < 2; half++) {
            int r = row0 + wm*32 + mt*16 + g + half*8;
            if (r >= re) continue;
            float rsc = (EPI == 3) ? rowscale[r] : 1.f;
            #pragma unroll
            for (int nt = 0; nt < 8; nt++) {
                int cix = col0 + wn*64 + nt*8 + 2*t;
                float v0 = acc[mt][nt][half*2 + 0];
                float v1 = acc[mt][nt][half*2 + 1];
                if (EPI == 1) { v0 = epi_silu(v0); v1 = epi_silu(v1); }
                if (EPI == 3) { v0 *= rsc; v1 *= rsc; }
                float* p = Cb + (size_t)r*ldc + cix;
                if (EPI == 2) {
                    float2 o = *reinterpret_cast<float2*>(p);
                    v0 *= o.x; v1 *= o.y;
                }
                float2 vv; vv.x = v0; vv.y = v1;
                *reinterpret_cast<float2*>(p) = vv;
            }
        }
    }
    #undef AS
    #undef BS
}

// ---------------- split-K plane reduction ----------------
__global__ void reduce_kernel(const float* __restrict__ in, float* __restrict__ out,
                              int nwords, int nplanes, size_t plane) {
    int i = (blockIdx.x*256 + threadIdx.x) * 4;
    if (i >= nwords) return;
    float4 a = *reinterpret_cast<const float4*>(in + i);
    for (int p = 1; p < nplanes; p++) {
        float4 b = *reinterpret_cast<const float4*>(in + (size_t)p*plane + i);
        a.x += b.x; a.y += b.y; a.z += b.z; a.w += b.w;
    }
    *reinterpret_cast<float4*>(out + i) = a;
}

// ---------------- final combine ----------------
__global__ void combine_kernel(float* __restrict__ out) {
    int t = blockIdx.x;
    int c = blockIdx.y*256 + threadIdx.x;
    float s = out[(size_t)t*H_ + c];
    #pragma unroll
    for (int k = 0; k < KTOP; k++) {
        int slot = g_slot_of[t*KTOP + k];
        s += g_eout[(size_t)slot*H_ + c];
    }
    out[(size_t)t*H_ + c] = s;
}

// ---------------- host side ----------------
template<typename Tp>
static Tp* sym(const void* s) {
    void* p = nullptr;
    cudaGetSymbolAddress(&p, s);
    return (Tp*)p;
}

extern "C" void kernel_launch(void* const* d_in, const int* in_sizes, int n_in,
                              void* d_out, int out_size)
{
    const float* x      = (const float*)d_in[0];
    const float* gate_w = (const float*)d_in[1];
    const float* Rg     = (const float*)d_in[2];
    const float* Ru     = (const float*)d_in[3];
    const float* Rd     = (const float*)d_in[4];
    const float* Ug     = (const float*)d_in[5];
    const float* Cg     = (const float*)d_in[6];
    const float* Uu     = (const float*)d_in[7];
    const float* Cu     = (const float*)d_in[8];
    const float* Ud     = (const float*)d_in[9];
    const float* Cd     = (const float*)d_in[10];
    const float* s_Rg   = (const float*)d_in[11];
    const float* s_Ug   = (const float*)d_in[12];
    const float* s_Cg   = (const float*)d_in[13];
    const float* s_Ru   = (const float*)d_in[14];
    const float* s_Uu   = (const float*)d_in[15];
    const float* s_Cu   = (const float*)d_in[16];
    const float* s_Rd   = (const float*)d_in[17];
    const float* s_Ud   = (const float*)d_in[18];
    const float* s_Cd   = (const float*)d_in[19];
    float* out = (float*)d_out;

    float* p_projW = sym<float>(g_projW);
    float* p_sUW   = sym<float>(g_sUW);
    float* p_proj  = sym<float>(g_proj);
    float* p_st    = sym<float>(g_st);
    float* p_tg    = sym<float>(g_tg);
    float* p_tu    = sym<float>(g_tu);
    float* p_h     = sym<float>(g_h);
    float* p_rd    = sym<float>(g_rd);
    float* p_td    = sym<float>(g_td);
    float* p_sh    = sym<float>(g_sh);
    float* p_srd   = sym<float>(g_srd);
    float* p_std   = sym<float>(g_std);
    float* p_eout  = sym<float>(g_eout);
    float* p_split = sym<float>(g_split);
    int*   p_off   = sym<int>(g_off);
    int*   p_map   = sym<int>(g_tokslot);
    float* p_ws    = sym<float>(g_wslot);

    // raise dynamic smem cap on all used instantiations (host-side, idempotent)
    cudaFuncSetAttribute((const void*)gemm3<0,0>, cudaFuncAttributeMaxDynamicSharedMemorySize, GSMEM);
    cudaFuncSetAttribute((const void*)gemm3<1,0>, cudaFuncAttributeMaxDynamicSharedMemorySize, GSMEM);
    cudaFuncSetAttribute((const void*)gemm3<2,0>, cudaFuncAttributeMaxDynamicSharedMemorySize, GSMEM);
    cudaFuncSetAttribute((const void*)gemm3<3,0>, cudaFuncAttributeMaxDynamicSharedMemorySize, GSMEM);
    cudaFuncSetAttribute((const void*)gemm3<0,1>, cudaFuncAttributeMaxDynamicSharedMemorySize, GSMEM);
    cudaFuncSetAttribute((const void*)gemm3<1,1>, cudaFuncAttributeMaxDynamicSharedMemorySize, GSMEM);
    cudaFuncSetAttribute((const void*)gemm3<2,1>, cudaFuncAttributeMaxDynamicSharedMemorySize, GSMEM);
    cudaFuncSetAttribute((const void*)gemm3<0,2>, cudaFuncAttributeMaxDynamicSharedMemorySize, GSMEM);

    const size_t WPROJ = (size_t)R_*H_;

    // routing
    init_kernel<<<16,256>>>();
    gate_kernel<<<T_,256>>>(x, gate_w);
    scan_kernel<<<1,32>>>();
    compact_kernel<<<dim3(16,E_),256>>>();

    // pack projection weights (4 MB) and shared-U weights (128 KB)
    cudaMemcpyAsync(p_projW + 0*WPROJ, Rg,   WPROJ*4, cudaMemcpyDeviceToDevice);
    cudaMemcpyAsync(p_projW + 1*WPROJ, Ru,   WPROJ*4, cudaMemcpyDeviceToDevice);
    cudaMemcpyAsync(p_projW + 2*WPROJ, s_Rg, WPROJ*4, cudaMemcpyDeviceToDevice);
    cudaMemcpyAsync(p_projW + 3*WPROJ, s_Ru, WPROJ*4, cudaMemcpyDeviceToDevice);
    cudaMemcpyAsync(p_sUW + 0*R_*R_, s_Ug, (size_t)R_*R_*4, cudaMemcpyDeviceToDevice);
    cudaMemcpyAsync(p_sUW + 1*R_*R_, s_Uu, (size_t)R_*R_*4, cudaMemcpyDeviceToDevice);

    // 1. merged rank projections: [T,2048] x4 -> g_proj planes
    gemm3<0,1><<<dim3(32,1,4),256,GSMEM>>>(x,H_,0, p_projW,WPROJ,H_, p_proj,R_,(size_t)T_*R_,
                                           T_,R_,H_, nullptr,nullptr,nullptr);
    // 2/3. expert U-gate/up (gather rows by token)
    gemm3<0,0><<<dim3(32,1,E_),256,GSMEM>>>(p_proj,          R_,0, Ug,(size_t)R_*R_,R_, p_tg,R_,0,
                                            0,R_,R_, p_off,p_map,nullptr);
    gemm3<0,0><<<dim3(32,1,E_),256,GSMEM>>>(p_proj+(size_t)T_*R_,R_,0, Uu,(size_t)R_*R_,R_, p_tu,R_,0,
                                            0,R_,R_, p_off,p_map,nullptr);
    // 4/5. expert C-gate (silu) then C-up (mul-into)
    gemm3<1,0><<<dim3(32,11,E_),256,GSMEM>>>(p_tg,R_,0, Cg,(size_t)I_*R_,R_, p_h,I_,0,
                                             0,I_,R_, p_off,nullptr,nullptr);
    gemm3<2,0><<<dim3(32,11,E_),256,GSMEM>>>(p_tu,R_,0, Cu,(size_t)I_*R_,R_, p_h,I_,0,
                                             0,I_,R_, p_off,nullptr,nullptr);
    // 6. Rd: [TK,1408]->[TK,128], split-K=2 + reduce
    gemm3<0,2><<<dim3(128,1,2),256,GSMEM>>>(p_h,I_,0, Rd,0,I_, p_split,R_,(size_t)TK_*R_,
                                            TK_,R_,704, nullptr,nullptr,nullptr);
    reduce_kernel<<<(TK_*R_/4+255)/256,256>>>(p_split, p_rd, TK_*R_, 2, (size_t)TK_*R_);
    // 7. expert Ud
    gemm3<0,0><<<dim3(32,1,E_),256,GSMEM>>>(p_rd,R_,0, Ud,(size_t)R_*R_,R_, p_td,R_,0,
                                            0,R_,R_, p_off,nullptr,nullptr);
    // 8. expert Cd with routing weight
    gemm3<3,0><<<dim3(32,16,E_),256,GSMEM>>>(p_td,R_,0, Cd,(size_t)H_*R_,R_, p_eout,H_,0,
                                             0,H_,R_, p_off,nullptr,p_ws);
    // 9. merged shared U-gate/up
    gemm3<0,1><<<dim3(32,1,2),256,GSMEM>>>(p_proj+2*(size_t)T_*R_,R_,(size_t)T_*R_,
                                           p_sUW,(size_t)R_*R_,R_, p_st,R_,(size_t)T_*R_,
                                           T_,R_,R_, nullptr,nullptr,nullptr);
    // 10/11. shared C-gate (silu) then C-up (mul-into)
    gemm3<1,1><<<dim3(32,22,1),256,GSMEM>>>(p_st,R_,0, s_Cg,0,R_, p_sh,SI_,0,
                                            T_,SI_,R_, nullptr,nullptr,nullptr);
    gemm3<2,1><<<dim3(32,22,1),256,GSMEM>>>(p_st+(size_t)T_*R_,R_,0, s_Cu,0,R_, p_sh,SI_,0,
                                            T_,SI_,R_, nullptr,nullptr,nullptr);
    // 12. shared Rd: [T,2816]->[T,128], split-K=4 + reduce
    gemm3<0,2><<<dim3(32,1,4),256,GSMEM>>>(p_sh,SI_,0, s_Rd,0,SI_, p_split,R_,(size_t)T_*R_,
                                           T_,R_,704, nullptr,nullptr,nullptr);
    reduce_kernel<<<(T_*R_/4+255)/256,256>>>(p_split, p_srd, T_*R_, 4, (size_t)T_*R_);
    // 13. shared Ud
    gemm3<0,1><<<dim3(32,1,1),256,GSMEM>>>(p_srd,R_,0, s_Ud,0,R_, p_std,R_,0,
                                           T_,R_,R_, nullptr,nullptr,nullptr);
    // 14. shared Cd -> writes full d_out
    gemm3<0,1><<<dim3(32,16,1),256,GSMEM>>>(p_std,R_,0, s_Cd,0,R_, out,H_,0,
                                            T_,H_,R_, nullptr,nullptr,nullptr);

    // out[t] += this token's 4 expert-slot rows
    combine_kernel<<<dim3(T_,H_/256),256>>>(out);
}

// round 8
// speedup vs baseline: 1.4498x; 1.4498x over previous
#include <cuda_runtime.h>
#include <cuda_bf16.h>
#include <math.h>
#include <stdint.h>

#define T_   4096
#define H_   2048
#define E_   32
#define KTOP 4
#define I_   1408
#define R_   128
#define SI_  2816
#define TK_  (T_*KTOP)

// ======================= scratch (device globals) =======================
__device__ __align__(16) int   g_cnt[E_];
__device__ __align__(16) int   g_off[E_+1];
__device__ __align__(16) int   g_tok2d[E_*T_];
__device__ __align__(16) float g_w2d[E_*T_];
__device__ __align__(16) int   g_tokslot[TK_];
__device__ __align__(16) float g_wslot[TK_];
__device__ __align__(16) int   g_slot_of[TK_];
__device__ __align__(16) int   g_tokc[T_];

// split bf16 hi/lo buffers (lo plane(s) after hi plane(s))
__device__ __align__(16) __nv_bfloat16 g_xs    [2u*T_*H_];
__device__ __align__(16) __nv_bfloat16 g_w_proj[2u*4*R_*H_];
__device__ __align__(16) __nv_bfloat16 g_w_Ug  [2u*E_*R_*R_];
__device__ __align__(16) __nv_bfloat16 g_w_Uu  [2u*E_*R_*R_];
__device__ __align__(16) __nv_bfloat16 g_w_Ud  [2u*E_*R_*R_];
__device__ __align__(16) __nv_bfloat16 g_w_Cg  [2u*E_*I_*R_];
__device__ __align__(16) __nv_bfloat16 g_w_Cu  [2u*E_*I_*R_];
__device__ __align__(16) __nv_bfloat16 g_w_Cd  [2u*E_*H_*R_];
__device__ __align__(16) __nv_bfloat16 g_w_Rd  [2u*R_*I_];
__device__ __align__(16) __nv_bfloat16 g_w_sU  [2u*2*R_*R_];
__device__ __align__(16) __nv_bfloat16 g_w_sCg [2u*SI_*R_];
__device__ __align__(16) __nv_bfloat16 g_w_sCu [2u*SI_*R_];
__device__ __align__(16) __nv_bfloat16 g_w_sRd [2u*R_*SI_];
__device__ __align__(16) __nv_bfloat16 g_w_sUd [2u*R_*R_];
__device__ __align__(16) __nv_bfloat16 g_w_sCd [2u*H_*R_];

__device__ __align__(16) __nv_bfloat16 g_proj_s[2u*4*T_*R_];
__device__ __align__(16) __nv_bfloat16 g_tg_s  [2u*TK_*R_];
__device__ __align__(16) __nv_bfloat16 g_tu_s  [2u*TK_*R_];
__device__ __align__(16) float         g_hf    [(size_t)TK_*I_];
__device__ __align__(16) __nv_bfloat16 g_h_s   [2u*(size_t)TK_*I_];
__device__ __align__(16) __nv_bfloat16 g_rd_s  [2u*TK_*R_];
__device__ __align__(16) __nv_bfloat16 g_td_s  [2u*TK_*R_];
__device__ __align__(16) __nv_bfloat16 g_st_s  [2u*2*T_*R_];
__device__ __align__(16) float         g_shf   [(size_t)T_*SI_];
__device__ __align__(16) __nv_bfloat16 g_sh_s  [2u*(size_t)T_*SI_];
__device__ __align__(16) float         g_skp   [2u*T_*R_];
__device__ __align__(16) __nv_bfloat16 g_srd_s [2u*T_*R_];
__device__ __align__(16) __nv_bfloat16 g_std_s [2u*T_*R_];
__device__ __align__(16) float         g_eout  [(size_t)TK_*H_];

// ======================= helpers =======================
__device__ __forceinline__ uint32_t smem_u32_of(const void* p) {
    uint32_t a;
    asm("{ .reg .u64 t; cvta.to.shared.u64 t, %1; cvt.u32.u64 %0, t; }" : "=r"(a) : "l"(p));
    return a;
}
__device__ __forceinline__ void cpa16(uint32_t dst, const void* src, bool v) {
    int sz = v ? 16 : 0;
    asm volatile("cp.async.cg.shared.global [%0], [%1], 16, %2;\n" :: "r"(dst), "l"(src), "r"(sz));
}
__device__ __forceinline__ void ldm4(uint32_t* r, uint32_t addr) {
    asm volatile("ldmatrix.sync.aligned.m8n8.x4.shared.b16 {%0,%1,%2,%3}, [%4];"
                 : "=r"(r[0]), "=r"(r[1]), "=r"(r[2]), "=r"(r[3]) : "r"(addr));
}
__device__ __forceinline__ void mma_bf16(float* d, const uint32_t* a, const uint32_t* b) {
    asm volatile(
        "mma.sync.aligned.m16n8k16.row.col.f32.bf16.bf16.f32 "
        "{%0,%1,%2,%3},{%4,%5,%6,%7},{%8,%9},{%0,%1,%2,%3};\n"
        : "+f"(d[0]), "+f"(d[1]), "+f"(d[2]), "+f"(d[3])
        : "r"(a[0]), "r"(a[1]), "r"(a[2]), "r"(a[3]), "r"(b[0]), "r"(b[1]));
}
__device__ __forceinline__ float epi_silu(float v) { return v / (1.f + expf(-v)); }

// ======================= splitter =======================
__global__ void split_kernel(const float* __restrict__ src,
                             __nv_bfloat16* __restrict__ dh,
                             __nv_bfloat16* __restrict__ dl, size_t n) {
    size_t i = ((size_t)blockIdx.x*256 + threadIdx.x) * 4;
    if (i >= n) return;
    float4 v = *reinterpret_cast<const float4*>(src + i);
    __nv_bfloat16 h0 = __float2bfloat16(v.x), h1 = __float2bfloat16(v.y);
    __nv_bfloat16 h2 = __float2bfloat16(v.z), h3 = __float2bfloat16(v.w);
    __nv_bfloat16 l0 = __float2bfloat16(v.x - __bfloat162float(h0));
    __nv_bfloat16 l1 = __float2bfloat16(v.y - __bfloat162float(h1));
    __nv_bfloat16 l2 = __float2bfloat16(v.z - __bfloat162float(h2));
    __nv_bfloat16 l3 = __float2bfloat16(v.w - __bfloat162float(h3));
    *reinterpret_cast<__nv_bfloat162*>(dh + i)     = __halves2bfloat162(h0, h1);
    *reinterpret_cast<__nv_bfloat162*>(dh + i + 2) = __halves2bfloat162(h2, h3);
    *reinterpret_cast<__nv_bfloat162*>(dl + i)     = __halves2bfloat162(l0, l1);
    *reinterpret_cast<__nv_bfloat162*>(dl + i + 2) = __halves2bfloat162(l2, l3);
}

// ======================= routing =======================
__global__ void init_kernel() {
    int i = blockIdx.x*256 + threadIdx.x;
    if (i < E_) g_cnt[i] = 0;
    if (i < T_) g_tokc[i] = 0;
}
__global__ void gate_kernel(const float* __restrict__ x, const float* __restrict__ gw) {
    __shared__ float xs[H_];
    __shared__ float lg[E_];
    int t = blockIdx.x;
    const float* xr = x + (size_t)t*H_;
    for (int i = threadIdx.x; i < H_; i += 256) xs[i] = xr[i];
    __syncthreads();
    int warp = threadIdx.x >> 5, lane = threadIdx.x & 31;
    for (int e = warp; e < E_; e += 8) {
        const float* w = gw + (size_t)e*H_;
        float s = 0.f;
        for (int i = lane; i < H_; i += 32) s += xs[i]*w[i];
        #pragma unroll
        for (int o = 16; o; o >>= 1) s += __shfl_xor_sync(0xffffffffu, s, o);
        if (lane == 0) lg[e] = s;
    }
    __syncthreads();
    if (threadIdx.x == 0) {
        float mx = lg[0];
        for (int e = 1; e < E_; e++) mx = fmaxf(mx, lg[e]);
        float p[E_]; float sum = 0.f;
        for (int e = 0; e < E_; e++) { p[e] = expf(lg[e]-mx); sum += p[e]; }
        float inv = 1.f/sum;
        bool taken[E_];
        for (int e = 0; e < E_; e++) taken[e] = false;
        int idx[KTOP]; float w4[KTOP]; float ws = 0.f;
        for (int k = 0; k < KTOP; k++) {
            int best = 0; float bv = -1.f;
            for (int e = 0; e < E_; e++)
                if (!taken[e] && p[e] > bv) { bv = p[e]; best = e; }
            taken[best] = true; idx[k] = best; w4[k] = bv*inv; ws += w4[k];
        }
        float rn = 1.f/(ws + 1e-20f);
        for (int k = 0; k < KTOP; k++) {
            int e = idx[k];
            int pos = atomicAdd(&g_cnt[e], 1);
            g_tok2d[e*T_ + pos] = t;
            g_w2d [e*T_ + pos] = w4[k]*rn;
        }
    }
}
__global__ void scan_kernel() {
    if (threadIdx.x == 0 && blockIdx.x == 0) {
        int a = 0;
        for (int e = 0; e < E_; e++) { g_off[e] = a; a += g_cnt[e]; }
        g_off[E_] = a;
    }
}
__global__ void compact_kernel() {
    int e = blockIdx.y;
    int i = blockIdx.x*256 + threadIdx.x;
    if (i < g_cnt[e]) {
        int slot = g_off[e] + i;
        int tok = g_tok2d[e*T_ + i];
        g_tokslot[slot] = tok;
        g_wslot[slot]   = g_w2d[e*T_ + i];
        int c = atomicAdd(&g_tokc[tok], 1);
        g_slot_of[tok*KTOP + c] = slot;
    }
}

// ======================= bf16-split mma.sync GEMM =======================
// C[M,N] = epi(A[M,K] @ W[N,K]^T), 3-term bf16 split (al*bh + ah*bl + ah*bh)
// EPI: 0 split-store(bf16 hi/lo)  1 silu->fp32  2 (res*Mul)->split-store
//      3 rowscale->fp32           4 fp32
// ZMODE: 0 expert (off[] row ranges, W+z*wstride, optional rowmap gather)
//        1 dense (A+z*astride, W+z*wstride, C+z*cstride)
//        2 split-K (kbase=z*Kd, Cf+z*cstride)
// CTA tile 128x128, k-chunk 32 bf16, double-buffered cp.async; 8 warps 32x64.

#define ROWW  20                   // uint32 words per smem row (16 data + 4 pad)
#define TILEW (128*ROWW)           // words per operand tile
#define GSMEM (8*TILEW*4)          // 4 tiles x 2 stages = 81920 B

template<int EPI, int ZMODE>
__global__ __launch_bounds__(256, 2)
void bgemm(const __nv_bfloat16* __restrict__ Ah, int lda, size_t aplane, size_t astride,
           const __nv_bfloat16* __restrict__ Wh, int ldw, size_t wplane, size_t wstride,
           float* __restrict__ Cf,
           __nv_bfloat16* __restrict__ Ch, size_t cplane,
           const float* __restrict__ Mul,
           int ldc, size_t cstride,
           int M, int N, int Kd,
           const int* __restrict__ off,
           const int* __restrict__ rowmap,
           const float* __restrict__ rowscale)
{
    int z = blockIdx.z;
    int rs = 0, re = M;
    int kbase = 0;
    const __nv_bfloat16* A0 = Ah;
    const __nv_bfloat16* W0 = Wh;
    if (ZMODE == 0) { rs = off[z]; re = off[z+1]; W0 = Wh + (size_t)z*wstride; }
    else if (ZMODE == 1) { A0 = Ah + (size_t)z*astride; W0 = Wh + (size_t)z*wstride; }
    else { kbase = z*Kd; }

    int row0 = rs + blockIdx.x * 128;
    if (row0 >= re) return;
    int col0 = blockIdx.y * 128;

    extern __shared__ uint32_t smw[];
    uint32_t sb = smem_u32_of(smw);

    int tid = threadIdx.x;
    int wid = tid >> 5, lane = tid & 31;
    int g = lane >> 2, t = lane & 3;
    int wm = wid & 3;        // 4 warps in m (32 rows each)
    int wn = wid >> 2;       // 2 warps in n (64 cols each)

    // ldmatrix per-lane offsets
    int aRow = ((lane >> 3) & 1)*8 + (lane & 7);
    int aCol = (lane >> 4)*4;
    int bRow = (lane >> 4)*8 + (lane & 7);
    int bCol = ((lane >> 3) & 1)*4;

    float acc[2][8][4];
    #pragma unroll
    for (int i = 0; i < 2; i++)
        #pragma unroll
        for (int j = 0; j < 8; j++)
            #pragma unroll
            for (int c = 0; c < 4; c++) acc[i][j][c] = 0.f;

    int iters = Kd / 32;

    auto stage = [&](int s, int kb) {
        uint32_t base = sb + (uint32_t)s*4*TILEW*4;
        #pragma unroll
        for (int it = 0; it < 8; it++) {
            int id = tid + it*256;
            int tile = id >> 9;           // 0..3 : Ah, Al, Bh, Bl
            int rem = id & 511;
            int row = rem >> 2;
            int seg = rem & 3;            // 16B (8 bf16) segment
            uint32_t dst = base + (uint32_t)(tile*TILEW + row*ROWW + seg*4)*4;
            int kpos = kbase + kb + seg*8;
            if (tile < 2) {
                int r = row0 + row;
                bool v = (r < re);
                int ar = 0;
                if (v) ar = (ZMODE == 0 && rowmap) ? rowmap[r] : r;
                const __nv_bfloat16* Ab = (tile == 0) ? A0 : (A0 + aplane);
                cpa16(dst, Ab + (size_t)ar*lda + kpos, v);
            } else {
                int n = col0 + row;
                const __nv_bfloat16* Wb = (tile == 2) ? W0 : (W0 + wplane);
                cpa16(dst, Wb + (size_t)n*ldw + kpos, true);
            }
        }
    };

    stage(0, 0);
    asm volatile("cp.async.commit_group;\n");

    for (int kt = 0; kt < iters; kt++) {
        if (kt + 1 < iters) {
            stage((kt+1) & 1, (kt+1)*32);
            asm volatile("cp.async.commit_group;\n");
            asm volatile("cp.async.wait_group 1;\n");
        } else {
            asm volatile("cp.async.wait_group 0;\n");
        }
        __syncthreads();
        uint32_t base = sb + (uint32_t)(kt & 1)*4*TILEW*4;

        #pragma unroll
        for (int kk = 0; kk < 16; kk += 8) {   // two k16 sub-chunks
            uint32_t aH[2][4], aL[2][4];
            #pragma unroll
            for (int mt = 0; mt < 2; mt++) {
                uint32_t ro = (uint32_t)((wm*32 + mt*16 + aRow)*ROWW + kk + aCol)*4;
                ldm4(aH[mt], base + 0*TILEW*4 + ro);
                ldm4(aL[mt], base + 1*TILEW*4 + ro);
            }
            #pragma unroll
            for (int half = 0; half < 2; half++) {
                uint32_t bH[2][4], bL[2][4];
                #pragma unroll
                for (int pp = 0; pp < 2; pp++) {
                    int p2 = half*2 + pp;
                    uint32_t ro = (uint32_t)((wn*64 + p2*16 + bRow)*ROWW + kk + bCol)*4;
                    ldm4(bH[pp], base + 2*TILEW*4 + ro);
                    ldm4(bL[pp], base + 3*TILEW*4 + ro);
                }
                #pragma unroll
                for (int mt = 0; mt < 2; mt++) {
                    #pragma unroll
                    for (int n4 = 0; n4 < 4; n4++) {
                        int nt = half*4 + n4;
                        int pp = n4 >> 1, w = (n4 & 1)*2;
                        mma_bf16(acc[mt][nt], aL[mt], &bH[pp][w]);
                        mma_bf16(acc[mt][nt], aH[mt], &bL[pp][w]);
                        mma_bf16(acc[mt][nt], aH[mt], &bH[pp][w]);
                    }
                }
            }
        }
        __syncthreads();
    }

    // epilogue: d0,d1 -> (row g, cols 2t,2t+1); d2,d3 -> (row g+8)
    float* Cf_z = Cf;
    __nv_bfloat16* Ch_z = Ch;
    if (ZMODE == 1 || ZMODE == 2) { Cf_z = Cf + (size_t)z*cstride; Ch_z = Ch + (size_t)z*cstride; }
    #pragma unroll
    for (int mt = 0; mt < 2; mt++) {
        #pragma unroll
        for (int half = 0; half < 2; half++) {
            int r = row0 + wm*32 + mt*16 + g + half*8;
            if (r >= re) continue;
            float rsc = (EPI == 3) ? rowscale[r] : 1.f;
            #pragma unroll
            for (int nt = 0; nt < 8; nt++) {
                int cix = col0 + wn*64 + nt*8 + 2*t;
                float v0 = acc[mt][nt][half*2 + 0];
                float v1 = acc[mt][nt][half*2 + 1];
                if (EPI == 1) { v0 = epi_silu(v0); v1 = epi_silu(v1); }
                if (EPI == 3) { v0 *= rsc; v1 *= rsc; }
                if (EPI == 2) {
                    float2 m = *reinterpret_cast<const float2*>(Mul + (size_t)r*ldc + cix);
                    v0 *= m.x; v1 *= m.y;
                }
                if (EPI == 0 || EPI == 2) {
                    __nv_bfloat16 h0 = __float2bfloat16(v0);
                    __nv_bfloat16 h1 = __float2bfloat16(v1);
                    __nv_bfloat16 l0 = __float2bfloat16(v0 - __bfloat162float(h0));
                    __nv_bfloat16 l1 = __float2bfloat16(v1 - __bfloat162float(h1));
                    __nv_bfloat16* p = Ch_z + (size_t)r*ldc + cix;
                    *reinterpret_cast<__nv_bfloat162*>(p)          = __halves2bfloat162(h0, h1);
                    *reinterpret_cast<__nv_bfloat162*>(p + cplane) = __halves2bfloat162(l0, l1);
                } else {
                    float2 vv; vv.x = v0; vv.y = v1;
                    *reinterpret_cast<float2*>(Cf_z + (size_t)r*ldc + cix) = vv;
                }
            }
        }
    }
}

// ======================= split-K reduce -> split bf16 =======================
__global__ void reduce_split_kernel(const float* __restrict__ p0, const float* __restrict__ p1,
                                    __nv_bfloat16* __restrict__ dh, __nv_bfloat16* __restrict__ dl,
                                    int n) {
    int i = (blockIdx.x*256 + threadIdx.x) * 2;
    if (i >= n) return;
    float v0 = p0[i]   + p1[i];
    float v1 = p0[i+1] + p1[i+1];
    __nv_bfloat16 h0 = __float2bfloat16(v0), h1 = __float2bfloat16(v1);
    __nv_bfloat16 l0 = __float2bfloat16(v0 - __bfloat162float(h0));
    __nv_bfloat16 l1 = __float2bfloat16(v1 - __bfloat162float(h1));
    *reinterpret_cast<__nv_bfloat162*>(dh + i) = __halves2bfloat162(h0, h1);
    *reinterpret_cast<__nv_bfloat162*>(dl + i) = __halves2bfloat162(l0, l1);
}

// ======================= final combine =======================
__global__ void combine_kernel(float* __restrict__ out) {
    int t = blockIdx.x;
    int c = blockIdx.y*256 + threadIdx.x;
    float s = out[(size_t)t*H_ + c];
    #pragma unroll
    for (int k = 0; k < KTOP; k++) {
        int slot = g_slot_of[t*KTOP + k];
        s += g_eout[(size_t)slot*H_ + c];
    }
    out[(size_t)t*H_ + c] = s;
}

// ======================= host side =======================
template<typename Tp>
static Tp* sym(const void* s) {
    void* p = nullptr;
    cudaGetSymbolAddress(&p, s);
    return (Tp*)p;
}
static void split_launch(const float* src, __nv_bfloat16* dh, __nv_bfloat16* dl, size_t n) {
    split_kernel<<<(unsigned)(n/1024), 256>>>(src, dh, dl, n);
}

extern "C" void kernel_launch(void* const* d_in, const int* in_sizes, int n_in,
                              void* d_out, int out_size)
{
    const float* x      = (const float*)d_in[0];
    const float* gate_w = (const float*)d_in[1];
    const float* Rg     = (const float*)d_in[2];
    const float* Ru     = (const float*)d_in[3];
    const float* Rd     = (const float*)d_in[4];
    const float* Ug     = (const float*)d_in[5];
    const float* Cg     = (const float*)d_in[6];
    const float* Uu     = (const float*)d_in[7];
    const float* Cu     = (const float*)d_in[8];
    const float* Ud     = (const float*)d_in[9];
    const float* Cd     = (const float*)d_in[10];
    const float* s_Rg   = (const float*)d_in[11];
    const float* s_Ug   = (const float*)d_in[12];
    const float* s_Cg   = (const float*)d_in[13];
    const float* s_Ru   = (const float*)d_in[14];
    const float* s_Uu   = (const float*)d_in[15];
    const float* s_Cu   = (const float*)d_in[16];
    const float* s_Rd   = (const float*)d_in[17];
    const float* s_Ud   = (const float*)d_in[18];
    const float* s_Cd   = (const float*)d_in[19];
    float* out = (float*)d_out;

    __nv_bfloat16* p_xs    = sym<__nv_bfloat16>(g_xs);
    __nv_bfloat16* p_wproj = sym<__nv_bfloat16>(g_w_proj);
    __nv_bfloat16* p_wUg   = sym<__nv_bfloat16>(g_w_Ug);
    __nv_bfloat16* p_wUu   = sym<__nv_bfloat16>(g_w_Uu);
    __nv_bfloat16* p_wUd   = sym<__nv_bfloat16>(g_w_Ud);
    __nv_bfloat16* p_wCg   = sym<__nv_bfloat16>(g_w_Cg);
    __nv_bfloat16* p_wCu   = sym<__nv_bfloat16>(g_w_Cu);
    __nv_bfloat16* p_wCd   = sym<__nv_bfloat16>(g_w_Cd);
    __nv_bfloat16* p_wRd   = sym<__nv_bfloat16>(g_w_Rd);
    __nv_bfloat16* p_wsU   = sym<__nv_bfloat16>(g_w_sU);
    __nv_bfloat16* p_wsCg  = sym<__nv_bfloat16>(g_w_sCg);
    __nv_bfloat16* p_wsCu  = sym<__nv_bfloat16>(g_w_sCu);
    __nv_bfloat16* p_wsRd  = sym<__nv_bfloat16>(g_w_sRd);
    __nv_bfloat16* p_wsUd  = sym<__nv_bfloat16>(g_w_sUd);
    __nv_bfloat16* p_wsCd  = sym<__nv_bfloat16>(g_w_sCd);

    __nv_bfloat16* p_projs = sym<__nv_bfloat16>(g_proj_s);
    __nv_bfloat16* p_tgs   = sym<__nv_bfloat16>(g_tg_s);
    __nv_bfloat16* p_tus   = sym<__nv_bfloat16>(g_tu_s);
    float*         p_hf    = sym<float>(g_hf);
    __nv_bfloat16* p_hs    = sym<__nv_bfloat16>(g_h_s);
    __nv_bfloat16* p_rds   = sym<__nv_bfloat16>(g_rd_s);
    __nv_bfloat16* p_tds   = sym<__nv_bfloat16>(g_td_s);
    __nv_bfloat16* p_sts   = sym<__nv_bfloat16>(g_st_s);
    float*         p_shf   = sym<float>(g_shf);
    __nv_bfloat16* p_shs   = sym<__nv_bfloat16>(g_sh_s);
    float*         p_skp   = sym<float>(g_skp);
    __nv_bfloat16* p_srds  = sym<__nv_bfloat16>(g_srd_s);
    __nv_bfloat16* p_stds  = sym<__nv_bfloat16>(g_std_s);
    float*         p_eout  = sym<float>(g_eout);
    int*   p_off = sym<int>(g_off);
    int*   p_map = sym<int>(g_tokslot);
    float* p_ws  = sym<float>(g_wslot);

    cudaFuncSetAttribute((const void*)bgemm<0,0>, cudaFuncAttributeMaxDynamicSharedMemorySize, GSMEM);
    cudaFuncSetAttribute((const void*)bgemm<0,1>, cudaFuncAttributeMaxDynamicSharedMemorySize, GSMEM);
    cudaFuncSetAttribute((const void*)bgemm<1,0>, cudaFuncAttributeMaxDynamicSharedMemorySize, GSMEM);
    cudaFuncSetAttribute((const void*)bgemm<1,1>, cudaFuncAttributeMaxDynamicSharedMemorySize, GSMEM);
    cudaFuncSetAttribute((const void*)bgemm<2,0>, cudaFuncAttributeMaxDynamicSharedMemorySize, GSMEM);
    cudaFuncSetAttribute((const void*)bgemm<2,1>, cudaFuncAttributeMaxDynamicSharedMemorySize, GSMEM);
    cudaFuncSetAttribute((const void*)bgemm<3,0>, cudaFuncAttributeMaxDynamicSharedMemorySize, GSMEM);
    cudaFuncSetAttribute((const void*)bgemm<4,1>, cudaFuncAttributeMaxDynamicSharedMemorySize, GSMEM);
    cudaFuncSetAttribute((const void*)bgemm<4,2>, cudaFuncAttributeMaxDynamicSharedMemorySize, GSMEM);

    // ---- routing (fp32) ----
    init_kernel<<<16,256>>>();
    gate_kernel<<<T_,256>>>(x, gate_w);
    scan_kernel<<<1,32>>>();
    compact_kernel<<<dim3(16,E_),256>>>();

    // ---- split inputs/weights into bf16 hi/lo planes ----
    const size_t RH = (size_t)R_*H_, RR = (size_t)R_*R_;
    split_launch(x, p_xs, p_xs + (size_t)T_*H_, (size_t)T_*H_);
    split_launch(Rg,   p_wproj + 0*RH, p_wproj + 4*RH + 0*RH, RH);
    split_launch(Ru,   p_wproj + 1*RH, p_wproj + 4*RH + 1*RH, RH);
    split_launch(s_Rg, p_wproj + 2*RH, p_wproj + 4*RH + 2*RH, RH);
    split_launch(s_Ru, p_wproj + 3*RH, p_wproj + 4*RH + 3*RH, RH);
    split_launch(Ug, p_wUg, p_wUg + (size_t)E_*RR, (size_t)E_*RR);
    split_launch(Uu, p_wUu, p_wUu + (size_t)E_*RR, (size_t)E_*RR);
    split_launch(Ud, p_wUd, p_wUd + (size_t)E_*RR, (size_t)E_*RR);
    split_launch(Cg, p_wCg, p_wCg + (size_t)E_*I_*R_, (size_t)E_*I_*R_);
    split_launch(Cu, p_wCu, p_wCu + (size_t)E_*I_*R_, (size_t)E_*I_*R_);
    split_launch(Cd, p_wCd, p_wCd + (size_t)E_*H_*R_, (size_t)E_*H_*R_);
    split_launch(Rd, p_wRd, p_wRd + (size_t)R_*I_, (size_t)R_*I_);
    split_launch(s_Ug, p_wsU + 0*RR, p_wsU + 2*RR + 0*RR, RR);
    split_launch(s_Uu, p_wsU + 1*RR, p_wsU + 2*RR + 1*RR, RR);
    split_launch(s_Cg, p_wsCg, p_wsCg + (size_t)SI_*R_, (size_t)SI_*R_);
    split_launch(s_Cu, p_wsCu, p_wsCu + (size_t)SI_*R_, (size_t)SI_*R_);
    split_launch(s_Rd, p_wsRd, p_wsRd + (size_t)R_*SI_, (size_t)R_*SI_);
    split_launch(s_Ud, p_wsUd, p_wsUd + RR, RR);
    split_launch(s_Cd, p_wsCd, p_wsCd + (size_t)H_*R_, (size_t)H_*R_);

    const size_t TR = (size_t)T_*R_, TKR = (size_t)TK_*R_, TKI = (size_t)TK_*I_, TSI = (size_t)T_*SI_;
    const size_t SIR = (size_t)SI_*R_;

    // 1. rank projections: x @ {Rg,Ru,s_Rg,s_Ru}^T -> proj planes (split out)
    bgemm<0,1><<<dim3(32,1,4),256,GSMEM>>>(p_xs, H_, (size_t)T_*H_, 0,
        p_wproj, H_, 4*RH, RH, nullptr, p_projs, 4*TR, nullptr, R_, TR,
        T_, R_, H_, nullptr, nullptr, nullptr);
    // 2/3. expert U (gather token rows)
    bgemm<0,0><<<dim3(32,1,E_),256,GSMEM>>>(p_projs + 0*TR, R_, 4*TR, 0,
        p_wUg, R_, (size_t)E_*RR, RR, nullptr, p_tgs, TKR, nullptr, R_, 0,
        0, R_, R_, p_off, p_map, nullptr);
    bgemm<0,0><<<dim3(32,1,E_),256,GSMEM>>>(p_projs + 1*TR, R_, 4*TR, 0,
        p_wUu, R_, (size_t)E_*RR, RR, nullptr, p_tus, TKR, nullptr, R_, 0,
        0, R_, R_, p_off, p_map, nullptr);
    // 4. expert C-gate: silu -> fp32 hf
    bgemm<1,0><<<dim3(32,11,E_),256,GSMEM>>>(p_tgs, R_, TKR, 0,
        p_wCg, R_, (size_t)E_*I_*R_, (size_t)I_*R_, p_hf, nullptr, 0, nullptr, I_, 0,
        0, I_, R_, p_off, nullptr, nullptr);
    // 5. expert C-up: (res * hf) -> h split
    bgemm<2,0><<<dim3(32,11,E_),256,GSMEM>>>(p_tus, R_, TKR, 0,
        p_wCu, R_, (size_t)E_*I_*R_, (size_t)I_*R_, nullptr, p_hs, TKI, p_hf, I_, 0,
        0, I_, R_, p_off, nullptr, nullptr);
    // 6. Rd: [TK,1408] -> [TK,128]
    bgemm<0,1><<<dim3(128,1,1),256,GSMEM>>>(p_hs, I_, TKI, 0,
        p_wRd, I_, (size_t)R_*I_, 0, nullptr, p_rds, TKR, nullptr, R_, 0,
        TK_, R_, I_, nullptr, nullptr, nullptr);
    // 7. expert Ud
    bgemm<0,0><<<dim3(32,1,E_),256,GSMEM>>>(p_rds, R_, TKR, 0,
        p_wUd, R_, (size_t)E_*RR, RR, nullptr, p_tds, TKR, nullptr, R_, 0,
        0, R_, R_, p_off, nullptr, nullptr);
    // 8. expert Cd: rowscale -> eout fp32
    bgemm<3,0><<<dim3(32,16,E_),256,GSMEM>>>(p_tds, R_, TKR, 0,
        p_wCd, R_, (size_t)E_*H_*R_, (size_t)H_*R_, p_eout, nullptr, 0, nullptr, H_, 0,
        0, H_, R_, p_off, nullptr, p_ws);
    // 9. shared U (z over gate/up)
    bgemm<0,1><<<dim3(32,1,2),256,GSMEM>>>(p_projs + 2*TR, R_, 4*TR, TR,
        p_wsU, R_, 2*RR, RR, nullptr, p_sts, 2*TR, nullptr, R_, TR,
        T_, R_, R_, nullptr, nullptr, nullptr);
    // 10. shared C-gate: silu -> shf  (wplane = SI*R, fixed)
    bgemm<1,1><<<dim3(32,22,1),256,GSMEM>>>(p_sts + 0*TR, R_, 2*TR, 0,
        p_wsCg, R_, SIR, 0, p_shf, nullptr, 0, nullptr, SI_, 0,
        T_, SI_, R_, nullptr, nullptr, nullptr);
    // 11. shared C-up: (res * shf) -> sh split  (wplane = SI*R, fixed)
    bgemm<2,1><<<dim3(32,22,1),256,GSMEM>>>(p_sts + 1*TR, R_, 2*TR, 0,
        p_wsCu, R_, SIR, 0, nullptr, p_shs, TSI, p_shf, SI_, 0,
        T_, SI_, R_, nullptr, nullptr, nullptr);
    // 12. shared Rd: split-K=2 -> fp32 partials, reduce -> srd split
    bgemm<4,2><<<dim3(32,1,2),256,GSMEM>>>(p_shs, SI_, TSI, 0,
        p_wsRd, SI_, (size_t)R_*SI_, 0, p_skp, nullptr, 0, nullptr, R_, TR,
        T_, R_, SI_/2, nullptr, nullptr, nullptr);
    reduce_split_kernel<<<(T_*R_/2+255)/256,256>>>(p_skp, p_skp + TR, p_srds, p_srds + TR, T_*R_);
    // 13. shared Ud
    bgemm<0,1><<<dim3(32,1,1),256,GSMEM>>>(p_srds, R_, TR, 0,
        p_wsUd, R_, RR, 0, nullptr, p_stds, TR, nullptr, R_, 0,
        T_, R_, R_, nullptr, nullptr, nullptr);
    // 14. shared Cd -> full d_out fp32
    bgemm<4,1><<<dim3(32,16,1),256,GSMEM>>>(p_stds, R_, TR, 0,
        p_wsCd, R_, (size_t)H_*R_, 0, out, nullptr, 0, nullptr, H_, 0,
        T_, H_, R_, nullptr, nullptr, nullptr);

    // out[t] += this token's 4 expert-slot rows
    combine_kernel<<<dim3(T_,H_/256),256>>>(out);
}

// round 9
// speedup vs baseline: 1.5045x; 1.0378x over previous
#include <cuda_runtime.h>
#include <cuda_bf16.h>
#include <math.h>
#include <stdint.h>

#define T_   4096
#define H_   2048
#define E_   32
#define KTOP 4
#define I_   1408
#define R_   128
#define SI_  2816
#define TK_  (T_*KTOP)

// ======================= scratch (device globals) =======================
__device__ __align__(16) int   g_cnt[E_];
__device__ __align__(16) int   g_off[E_+1];
__device__ __align__(16) int   g_tok2d[E_*T_];
__device__ __align__(16) float g_w2d[E_*T_];
__device__ __align__(16) int   g_tokslot[TK_];
__device__ __align__(16) float g_wslot[TK_];
__device__ __align__(16) int   g_slot_of[TK_];
__device__ __align__(16) int   g_tokc[T_];

// split bf16 hi/lo buffers (lo plane(s) after hi plane(s))
__device__ __align__(16) __nv_bfloat16 g_xs    [2u*T_*H_];
__device__ __align__(16) __nv_bfloat16 g_w_proj[2u*4*R_*H_];
__device__ __align__(16) __nv_bfloat16 g_w_Ug  [2u*E_*R_*R_];
__device__ __align__(16) __nv_bfloat16 g_w_Uu  [2u*E_*R_*R_];
__device__ __align__(16) __nv_bfloat16 g_w_Ud  [2u*E_*R_*R_];
__device__ __align__(16) __nv_bfloat16 g_w_Cg  [2u*E_*I_*R_];
__device__ __align__(16) __nv_bfloat16 g_w_Cu  [2u*E_*I_*R_];
__device__ __align__(16) __nv_bfloat16 g_w_Cd  [2u*E_*H_*R_];
__device__ __align__(16) __nv_bfloat16 g_w_Rd  [2u*R_*I_];
__device__ __align__(16) __nv_bfloat16 g_w_sU  [2u*2*R_*R_];
__device__ __align__(16) __nv_bfloat16 g_w_sCg [2u*SI_*R_];
__device__ __align__(16) __nv_bfloat16 g_w_sCu [2u*SI_*R_];
__device__ __align__(16) __nv_bfloat16 g_w_sRd [2u*R_*SI_];
__device__ __align__(16) __nv_bfloat16 g_w_sUd [2u*R_*R_];
__device__ __align__(16) __nv_bfloat16 g_w_sCd [2u*H_*R_];

__device__ __align__(16) __nv_bfloat16 g_proj_s[2u*4*T_*R_];
__device__ __align__(16) __nv_bfloat16 g_tg_s  [2u*TK_*R_];
__device__ __align__(16) __nv_bfloat16 g_tu_s  [2u*TK_*R_];
__device__ __align__(16) float         g_hf    [(size_t)TK_*I_];
__device__ __align__(16) __nv_bfloat16 g_h_s   [2u*(size_t)TK_*I_];
__device__ __align__(16) __nv_bfloat16 g_rd_s  [2u*TK_*R_];
__device__ __align__(16) __nv_bfloat16 g_td_s  [2u*TK_*R_];
__device__ __align__(16) __nv_bfloat16 g_st_s  [2u*2*T_*R_];
__device__ __align__(16) float         g_shf   [(size_t)T_*SI_];
__device__ __align__(16) __nv_bfloat16 g_sh_s  [2u*(size_t)T_*SI_];
__device__ __align__(16) float         g_skp   [2u*T_*R_];
__device__ __align__(16) __nv_bfloat16 g_srd_s [2u*T_*R_];
__device__ __align__(16) __nv_bfloat16 g_std_s [2u*T_*R_];
__device__ __align__(16) float         g_eout  [(size_t)TK_*H_];

// ======================= helpers =======================
__device__ __forceinline__ uint32_t smem_u32_of(const void* p) {
    uint32_t a;
    asm("{ .reg .u64 t; cvta.to.shared.u64 t, %1; cvt.u32.u64 %0, t; }" : "=r"(a) : "l"(p));
    return a;
}
__device__ __forceinline__ void cpa16(uint32_t dst, const void* src, bool v) {
    int sz = v ? 16 : 0;
    asm volatile("cp.async.cg.shared.global [%0], [%1], 16, %2;\n" :: "r"(dst), "l"(src), "r"(sz));
}
__device__ __forceinline__ void ldm4(uint32_t* r, uint32_t addr) {
    asm volatile("ldmatrix.sync.aligned.m8n8.x4.shared.b16 {%0,%1,%2,%3}, [%4];"
                 : "=r"(r[0]), "=r"(r[1]), "=r"(r[2]), "=r"(r[3]) : "r"(addr));
}
__device__ __forceinline__ void mma_bf16(float* d, const uint32_t* a, const uint32_t* b) {
    asm volatile(
        "mma.sync.aligned.m16n8k16.row.col.f32.bf16.bf16.f32 "
        "{%0,%1,%2,%3},{%4,%5,%6,%7},{%8,%9},{%0,%1,%2,%3};\n"
        : "+f"(d[0]), "+f"(d[1]), "+f"(d[2]), "+f"(d[3])
        : "r"(a[0]), "r"(a[1]), "r"(a[2]), "r"(a[3]), "r"(b[0]), "r"(b[1]));
}
__device__ __forceinline__ float epi_silu(float v) { return v / (1.f + expf(-v)); }

// ======================= mega-split: all hi/lo jobs in one launch =======================
#define NJOBS 19
struct SplitJobs {
    const float*   src[NJOBS];
    __nv_bfloat16* dh [NJOBS];
    __nv_bfloat16* dl [NJOBS];
    unsigned       n  [NJOBS];        // element count
    unsigned       sb [NJOBS+1];      // start block (prefix)
};

__global__ void megasplit_kernel(SplitJobs J) {
    unsigned bx = blockIdx.x;
    int j = 0;
    #pragma unroll
    for (int k = 0; k < NJOBS; k++) if (bx >= J.sb[k+1]) j = k+1;
    unsigned local = bx - J.sb[j];
    size_t i = ((size_t)local*256 + threadIdx.x) * 4;
    if (i >= J.n[j]) return;
    const float* src = J.src[j];
    __nv_bfloat16* dh = J.dh[j];
    __nv_bfloat16* dl = J.dl[j];
    float4 v = *reinterpret_cast<const float4*>(src + i);
    __nv_bfloat16 h0 = __float2bfloat16(v.x), h1 = __float2bfloat16(v.y);
    __nv_bfloat16 h2 = __float2bfloat16(v.z), h3 = __float2bfloat16(v.w);
    __nv_bfloat16 l0 = __float2bfloat16(v.x - __bfloat162float(h0));
    __nv_bfloat16 l1 = __float2bfloat16(v.y - __bfloat162float(h1));
    __nv_bfloat16 l2 = __float2bfloat16(v.z - __bfloat162float(h2));
    __nv_bfloat16 l3 = __float2bfloat16(v.w - __bfloat162float(h3));
    *reinterpret_cast<__nv_bfloat162*>(dh + i)     = __halves2bfloat162(h0, h1);
    *reinterpret_cast<__nv_bfloat162*>(dh + i + 2) = __halves2bfloat162(h2, h3);
    *reinterpret_cast<__nv_bfloat162*>(dl + i)     = __halves2bfloat162(l0, l1);
    *reinterpret_cast<__nv_bfloat162*>(dl + i + 2) = __halves2bfloat162(l2, l3);
}

// ======================= routing =======================
__global__ void init_kernel() {
    int i = blockIdx.x*256 + threadIdx.x;
    if (i < E_) g_cnt[i] = 0;
    if (i < T_) g_tokc[i] = 0;
}
__global__ void gate_kernel(const float* __restrict__ x, const float* __restrict__ gw) {
    __shared__ float xs[H_];
    __shared__ float lg[E_];
    int t = blockIdx.x;
    const float* xr = x + (size_t)t*H_;
    for (int i = threadIdx.x; i < H_; i += 256) xs[i] = xr[i];
    __syncthreads();
    int warp = threadIdx.x >> 5, lane = threadIdx.x & 31;
    for (int e = warp; e < E_; e += 8) {
        const float* w = gw + (size_t)e*H_;
        float s = 0.f;
        for (int i = lane; i < H_; i += 32) s += xs[i]*w[i];
        #pragma unroll
        for (int o = 16; o; o >>= 1) s += __shfl_xor_sync(0xffffffffu, s, o);
        if (lane == 0) lg[e] = s;
    }
    __syncthreads();
    if (threadIdx.x == 0) {
        float mx = lg[0];
        for (int e = 1; e < E_; e++) mx = fmaxf(mx, lg[e]);
        float p[E_]; float sum = 0.f;
        for (int e = 0; e < E_; e++) { p[e] = expf(lg[e]-mx); sum += p[e]; }
        float inv = 1.f/sum;
        bool taken[E_];
        for (int e = 0; e < E_; e++) taken[e] = false;
        int idx[KTOP]; float w4[KTOP]; float ws = 0.f;
        for (int k = 0; k < KTOP; k++) {
            int best = 0; float bv = -1.f;
            for (int e = 0; e < E_; e++)
                if (!taken[e] && p[e] > bv) { bv = p[e]; best = e; }
            taken[best] = true; idx[k] = best; w4[k] = bv*inv; ws += w4[k];
        }
        float rn = 1.f/(ws + 1e-20f);
        for (int k = 0; k < KTOP; k++) {
            int e = idx[k];
            int pos = atomicAdd(&g_cnt[e], 1);
            g_tok2d[e*T_ + pos] = t;
            g_w2d [e*T_ + pos] = w4[k]*rn;
        }
    }
}
__global__ void scan_kernel() {
    if (threadIdx.x == 0 && blockIdx.x == 0) {
        int a = 0;
        for (int e = 0; e < E_; e++) { g_off[e] = a; a += g_cnt[e]; }
        g_off[E_] = a;
    }
}
__global__ void compact_kernel() {
    int e = blockIdx.y;
    int i = blockIdx.x*256 + threadIdx.x;
    if (i < g_cnt[e]) {
        int slot = g_off[e] + i;
        int tok = g_tok2d[e*T_ + i];
        g_tokslot[slot] = tok;
        g_wslot[slot]   = g_w2d[e*T_ + i];
        int c = atomicAdd(&g_tokc[tok], 1);
        g_slot_of[tok*KTOP + c] = slot;
    }
}

// ======================= bf16-split mma.sync GEMM =======================
// C[M,N] = epi(A[M,K] @ W[N,K]^T), 3-term bf16 split (al*bh + ah*bl + ah*bh)
// EPI: 0 split-store(bf16 hi/lo)  1 silu->fp32  2 (res*Mul)->split-store
//      3 rowscale->fp32           4 fp32        5 fp32 + gather-add 4 expert slots
// ZMODE: 0 expert (off[] row ranges, W+z*wstride, optional rowmap gather)
//        1 dense (A+z*astride, W+z*wstride, C+z*cstride)
//        2 split-K (kbase=z*Kd, Cf+z*cstride)
// CTA tile 128x128, k-chunk 32 bf16, double-buffered cp.async; 8 warps 32x64.

#define ROWW  20                   // uint32 words per smem row (16 data + 4 pad)
#define TILEW (128*ROWW)           // words per operand tile
#define GSMEM (8*TILEW*4)          // 4 tiles x 2 stages = 81920 B

template<int EPI, int ZMODE>
__global__ __launch_bounds__(256, 2)
void bgemm(const __nv_bfloat16* __restrict__ Ah, int lda, size_t aplane, size_t astride,
           const __nv_bfloat16* __restrict__ Wh, int ldw, size_t wplane, size_t wstride,
           float* __restrict__ Cf,
           __nv_bfloat16* __restrict__ Ch, size_t cplane,
           const float* __restrict__ Mul,
           int ldc, size_t cstride,
           int M, int N, int Kd,
           const int* __restrict__ off,
           const int* __restrict__ rowmap,
           const float* __restrict__ rowscale)
{
    int z = blockIdx.z;
    int rs = 0, re = M;
    int kbase = 0;
    const __nv_bfloat16* A0 = Ah;
    const __nv_bfloat16* W0 = Wh;
    if (ZMODE == 0) { rs = off[z]; re = off[z+1]; W0 = Wh + (size_t)z*wstride; }
    else if (ZMODE == 1) { A0 = Ah + (size_t)z*astride; W0 = Wh + (size_t)z*wstride; }
    else { kbase = z*Kd; }

    int row0 = rs + blockIdx.x * 128;
    if (row0 >= re) return;
    int col0 = blockIdx.y * 128;

    extern __shared__ uint32_t smw[];
    uint32_t sb = smem_u32_of(smw);

    int tid = threadIdx.x;
    int wid = tid >> 5, lane = tid & 31;
    int g = lane >> 2, t = lane & 3;
    int wm = wid & 3;        // 4 warps in m (32 rows each)
    int wn = wid >> 2;       // 2 warps in n (64 cols each)

    // ldmatrix per-lane offsets
    int aRow = ((lane >> 3) & 1)*8 + (lane & 7);
    int aCol = (lane >> 4)*4;
    int bRow = (lane >> 4)*8 + (lane & 7);
    int bCol = ((lane >> 3) & 1)*4;

    float acc[2][8][4];
    #pragma unroll
    for (int i = 0; i < 2; i++)
        #pragma unroll
        for (int j = 0; j < 8; j++)
            #pragma unroll
            for (int c = 0; c < 4; c++) acc[i][j][c] = 0.f;

    int iters = Kd / 32;

    auto stage = [&](int s, int kb) {
        uint32_t base = sb + (uint32_t)s*4*TILEW*4;
        #pragma unroll
        for (int it = 0; it < 8; it++) {
            int id = tid + it*256;
            int tile = id >> 9;           // 0..3 : Ah, Al, Bh, Bl
            int rem = id & 511;
            int row = rem >> 2;
            int seg = rem & 3;            // 16B (8 bf16) segment
            uint32_t dst = base + (uint32_t)(tile*TILEW + row*ROWW + seg*4)*4;
            int kpos = kbase + kb + seg*8;
            if (tile < 2) {
                int r = row0 + row;
                bool v = (r < re);
                int ar = 0;
                if (v) ar = (ZMODE == 0 && rowmap) ? rowmap[r] : r;
                const __nv_bfloat16* Ab = (tile == 0) ? A0 : (A0 + aplane);
                cpa16(dst, Ab + (size_t)ar*lda + kpos, v);
            } else {
                int n = col0 + row;
                const __nv_bfloat16* Wb = (tile == 2) ? W0 : (W0 + wplane);
                cpa16(dst, Wb + (size_t)n*ldw + kpos, true);
            }
        }
    };

    stage(0, 0);
    asm volatile("cp.async.commit_group;\n");

    for (int kt = 0; kt < iters; kt++) {
        if (kt + 1 < iters) {
            stage((kt+1) & 1, (kt+1)*32);
            asm volatile("cp.async.commit_group;\n");
            asm volatile("cp.async.wait_group 1;\n");
        } else {
            asm volatile("cp.async.wait_group 0;\n");
        }
        __syncthreads();
        uint32_t base = sb + (uint32_t)(kt & 1)*4*TILEW*4;

        #pragma unroll
        for (int kk = 0; kk < 16; kk += 8) {   // two k16 sub-chunks
            uint32_t aH[2][4], aL[2][4];
            #pragma unroll
            for (int mt = 0; mt < 2; mt++) {
                uint32_t ro = (uint32_t)((wm*32 + mt*16 + aRow)*ROWW + kk + aCol)*4;
                ldm4(aH[mt], base + 0*TILEW*4 + ro);
                ldm4(aL[mt], base + 1*TILEW*4 + ro);
            }
            #pragma unroll
            for (int half = 0; half < 2; half++) {
                uint32_t bH[2][4], bL[2][4];
                #pragma unroll
                for (int pp = 0; pp < 2; pp++) {
                    int p2 = half*2 + pp;
                    uint32_t ro = (uint32_t)((wn*64 + p2*16 + bRow)*ROWW + kk + bCol)*4;
                    ldm4(bH[pp], base + 2*TILEW*4 + ro);
                    ldm4(bL[pp], base + 3*TILEW*4 + ro);
                }
                #pragma unroll
                for (int mt = 0; mt < 2; mt++) {
                    #pragma unroll
                    for (int n4 = 0; n4 < 4; n4++) {
                        int nt = half*4 + n4;
                        int pp = n4 >> 1, w = (n4 & 1)*2;
                        mma_bf16(acc[mt][nt], aL[mt], &bH[pp][w]);
                        mma_bf16(acc[mt][nt], aH[mt], &bL[pp][w]);
                        mma_bf16(acc[mt][nt], aH[mt], &bH[pp][w]);
                    }
                }
            }
        }
        __syncthreads();
    }

    // epilogue: d0,d1 -> (row g, cols 2t,2t+1); d2,d3 -> (row g+8)
    float* Cf_z = Cf;
    __nv_bfloat16* Ch_z = Ch;
    if (ZMODE == 1 || ZMODE == 2) { Cf_z = Cf + (size_t)z*cstride; Ch_z = Ch + (size_t)z*cstride; }
    #pragma unroll
    for (int mt = 0; mt < 2; mt++) {
        #pragma unroll
        for (int half = 0; half < 2; half++) {
            int r = row0 + wm*32 + mt*16 + g + half*8;
            if (r >= re) continue;
            float rsc = (EPI == 3) ? rowscale[r] : 1.f;
            int sl[KTOP];
            if (EPI == 5) {
                #pragma unroll
                for (int k = 0; k < KTOP; k++) sl[k] = g_slot_of[r*KTOP + k];
            }
            #pragma unroll
            for (int nt = 0; nt < 8; nt++) {
                int cix = col0 + wn*64 + nt*8 + 2*t;
                float v0 = acc[mt][nt][half*2 + 0];
                float v1 = acc[mt][nt][half*2 + 1];
                if (EPI == 1) { v0 = epi_silu(v0); v1 = epi_silu(v1); }
                if (EPI == 3) { v0 *= rsc; v1 *= rsc; }
                if (EPI == 2) {
                    float2 m = *reinterpret_cast<const float2*>(Mul + (size_t)r*ldc + cix);
                    v0 *= m.x; v1 *= m.y;
                }
                if (EPI == 5) {
                    #pragma unroll
                    for (int k = 0; k < KTOP; k++) {
                        float2 e2 = *reinterpret_cast<const float2*>(g_eout + (size_t)sl[k]*H_ + cix);
                        v0 += e2.x; v1 += e2.y;
                    }
                }
                if (EPI == 0 || EPI == 2) {
                    __nv_bfloat16 h0 = __float2bfloat16(v0);
                    __nv_bfloat16 h1 = __float2bfloat16(v1);
                    __nv_bfloat16 l0 = __float2bfloat16(v0 - __bfloat162float(h0));
                    __nv_bfloat16 l1 = __float2bfloat16(v1 - __bfloat162float(h1));
                    __nv_bfloat16* p = Ch_z + (size_t)r*ldc + cix;
                    *reinterpret_cast<__nv_bfloat162*>(p)          = __halves2bfloat162(h0, h1);
                    *reinterpret_cast<__nv_bfloat162*>(p + cplane) = __halves2bfloat162(l0, l1);
                } else {
                    float2 vv; vv.x = v0; vv.y = v1;
                    *reinterpret_cast<float2*>(Cf_z + (size_t)r*ldc + cix) = vv;
                }
            }
        }
    }
}

// ======================= split-K reduce -> split bf16 =======================
__global__ void reduce_split_kernel(const float* __restrict__ p0, const float* __restrict__ p1,
                                    __nv_bfloat16* __restrict__ dh, __nv_bfloat16* __restrict__ dl,
                                    int n) {
    int i = (blockIdx.x*256 + threadIdx.x) * 2;
    if (i >= n) return;
    float v0 = p0[i]   + p1[i];
    float v1 = p0[i+1] + p1[i+1];
    __nv_bfloat16 h0 = __float2bfloat16(v0), h1 = __float2bfloat16(v1);
    __nv_bfloat16 l0 = __float2bfloat16(v0 - __bfloat162float(h0));
    __nv_bfloat16 l1 = __float2bfloat16(v1 - __bfloat162float(h1));
    *reinterpret_cast<__nv_bfloat162*>(dh + i) = __halves2bfloat162(h0, h1);
    *reinterpret_cast<__nv_bfloat162*>(dl + i) = __halves2bfloat162(l0, l1);
}

// ======================= host side =======================
template<typename Tp>
static Tp* sym(const void* s) {
    void* p = nullptr;
    cudaGetSymbolAddress(&p, s);
    return (Tp*)p;
}

extern "C" void kernel_launch(void* const* d_in, const int* in_sizes, int n_in,
                              void* d_out, int out_size)
{
    const float* x      = (const float*)d_in[0];
    const float* gate_w = (const float*)d_in[1];
    const float* Rg     = (const float*)d_in[2];
    const float* Ru     = (const float*)d_in[3];
    const float* Rd     = (const float*)d_in[4];
    const float* Ug     = (const float*)d_in[5];
    const float* Cg     = (const float*)d_in[6];
    const float* Uu     = (const float*)d_in[7];
    const float* Cu     = (const float*)d_in[8];
    const float* Ud     = (const float*)d_in[9];
    const float* Cd     = (const float*)d_in[10];
    const float* s_Rg   = (const float*)d_in[11];
    const float* s_Ug   = (const float*)d_in[12];
    const float* s_Cg   = (const float*)d_in[13];
    const float* s_Ru   = (const float*)d_in[14];
    const float* s_Uu   = (const float*)d_in[15];
    const float* s_Cu   = (const float*)d_in[16];
    const float* s_Rd   = (const float*)d_in[17];
    const float* s_Ud   = (const float*)d_in[18];
    const float* s_Cd   = (const float*)d_in[19];
    float* out = (float*)d_out;

    __nv_bfloat16* p_xs    = sym<__nv_bfloat16>(g_xs);
    __nv_bfloat16* p_wproj = sym<__nv_bfloat16>(g_w_proj);
    __nv_bfloat16* p_wUg   = sym<__nv_bfloat16>(g_w_Ug);
    __nv_bfloat16* p_wUu   = sym<__nv_bfloat16>(g_w_Uu);
    __nv_bfloat16* p_wUd   = sym<__nv_bfloat16>(g_w_Ud);
    __nv_bfloat16* p_wCg   = sym<__nv_bfloat16>(g_w_Cg);
    __nv_bfloat16* p_wCu   = sym<__nv_bfloat16>(g_w_Cu);
    __nv_bfloat16* p_wCd   = sym<__nv_bfloat16>(g_w_Cd);
    __nv_bfloat16* p_wRd   = sym<__nv_bfloat16>(g_w_Rd);
    __nv_bfloat16* p_wsU   = sym<__nv_bfloat16>(g_w_sU);
    __nv_bfloat16* p_wsCg  = sym<__nv_bfloat16>(g_w_sCg);
    __nv_bfloat16* p_wsCu  = sym<__nv_bfloat16>(g_w_sCu);
    __nv_bfloat16* p_wsRd  = sym<__nv_bfloat16>(g_w_sRd);
    __nv_bfloat16* p_wsUd  = sym<__nv_bfloat16>(g_w_sUd);
    __nv_bfloat16* p_wsCd  = sym<__nv_bfloat16>(g_w_sCd);

    __nv_bfloat16* p_projs = sym<__nv_bfloat16>(g_proj_s);
    __nv_bfloat16* p_tgs   = sym<__nv_bfloat16>(g_tg_s);
    __nv_bfloat16* p_tus   = sym<__nv_bfloat16>(g_tu_s);
    float*         p_hf    = sym<float>(g_hf);
    __nv_bfloat16* p_hs    = sym<__nv_bfloat16>(g_h_s);
    __nv_bfloat16* p_rds   = sym<__nv_bfloat16>(g_rd_s);
    __nv_bfloat16* p_tds   = sym<__nv_bfloat16>(g_td_s);
    __nv_bfloat16* p_sts   = sym<__nv_bfloat16>(g_st_s);
    float*         p_shf   = sym<float>(g_shf);
    __nv_bfloat16* p_shs   = sym<__nv_bfloat16>(g_sh_s);
    float*         p_skp   = sym<float>(g_skp);
    __nv_bfloat16* p_srds  = sym<__nv_bfloat16>(g_srd_s);
    __nv_bfloat16* p_stds  = sym<__nv_bfloat16>(g_std_s);
    float*         p_eout  = sym<float>(g_eout);
    int*   p_off = sym<int>(g_off);
    int*   p_map = sym<int>(g_tokslot);
    float* p_ws  = sym<float>(g_wslot);

    cudaFuncSetAttribute((const void*)bgemm<0,0>, cudaFuncAttributeMaxDynamicSharedMemorySize, GSMEM);
    cudaFuncSetAttribute((const void*)bgemm<0,1>, cudaFuncAttributeMaxDynamicSharedMemorySize, GSMEM);
    cudaFuncSetAttribute((const void*)bgemm<1,0>, cudaFuncAttributeMaxDynamicSharedMemorySize, GSMEM);
    cudaFuncSetAttribute((const void*)bgemm<1,1>, cudaFuncAttributeMaxDynamicSharedMemorySize, GSMEM);
    cudaFuncSetAttribute((const void*)bgemm<2,0>, cudaFuncAttributeMaxDynamicSharedMemorySize, GSMEM);
    cudaFuncSetAttribute((const void*)bgemm<2,1>, cudaFuncAttributeMaxDynamicSharedMemorySize, GSMEM);
    cudaFuncSetAttribute((const void*)bgemm<3,0>, cudaFuncAttributeMaxDynamicSharedMemorySize, GSMEM);
    cudaFuncSetAttribute((const void*)bgemm<4,2>, cudaFuncAttributeMaxDynamicSharedMemorySize, GSMEM);
    cudaFuncSetAttribute((const void*)bgemm<5,1>, cudaFuncAttributeMaxDynamicSharedMemorySize, GSMEM);

    const size_t RH = (size_t)R_*H_, RR = (size_t)R_*R_;
    const size_t TR = (size_t)T_*R_, TKR = (size_t)TK_*R_, TKI = (size_t)TK_*I_, TSI = (size_t)T_*SI_;
    const size_t SIR = (size_t)SI_*R_;

    // ---- mega-split job table (one launch for all 19 hi/lo splits) ----
    SplitJobs J;
    {
        const float* srcs[NJOBS] = { x, Rg, Ru, s_Rg, s_Ru, Ug, Uu, Ud, Cg, Cu, Cd, Rd,
                                     s_Ug, s_Uu, s_Cg, s_Cu, s_Rd, s_Ud, s_Cd };
        __nv_bfloat16* dhs[NJOBS] = {
            p_xs, p_wproj + 0*RH, p_wproj + 1*RH, p_wproj + 2*RH, p_wproj + 3*RH,
            p_wUg, p_wUu, p_wUd, p_wCg, p_wCu, p_wCd, p_wRd,
            p_wsU + 0*RR, p_wsU + 1*RR, p_wsCg, p_wsCu, p_wsRd, p_wsUd, p_wsCd };
        __nv_bfloat16* dls[NJOBS] = {
            p_xs + (size_t)T_*H_, p_wproj + 4*RH + 0*RH, p_wproj + 4*RH + 1*RH,
            p_wproj + 4*RH + 2*RH, p_wproj + 4*RH + 3*RH,
            p_wUg + (size_t)E_*RR, p_wUu + (size_t)E_*RR, p_wUd + (size_t)E_*RR,
            p_wCg + (size_t)E_*I_*R_, p_wCu + (size_t)E_*I_*R_, p_wCd + (size_t)E_*H_*R_,
            p_wRd + (size_t)R_*I_,
            p_wsU + 2*RR + 0*RR, p_wsU + 2*RR + 1*RR,
            p_wsCg + SIR, p_wsCu + SIR, p_wsRd + (size_t)R_*SI_,
            p_wsUd + RR, p_wsCd + (size_t)H_*R_ };
        size_t ns[NJOBS] = { (size_t)T_*H_, RH, RH, RH, RH,
                             (size_t)E_*RR, (size_t)E_*RR, (size_t)E_*RR,
                             (size_t)E_*I_*R_, (size_t)E_*I_*R_, (size_t)E_*H_*R_,
                             (size_t)R_*I_, RR, RR, SIR, SIR, (size_t)R_*SI_, RR, (size_t)H_*R_ };
        unsigned acc = 0;
        for (int j = 0; j < NJOBS; j++) {
            J.src[j] = srcs[j]; J.dh[j] = dhs[j]; J.dl[j] = dls[j];
            J.n[j] = (unsigned)ns[j];
            J.sb[j] = acc;
            acc += (unsigned)((ns[j] + 1023) / 1024);
        }
        J.sb[NJOBS] = acc;
    }

    // ---- launch order chosen so an early in-stream launch is the big dense GEMM ----
    megasplit_kernel<<<J.sb[NJOBS],256>>>(J);                 // 0
    init_kernel<<<16,256>>>();                                 // 1
    gate_kernel<<<T_,256>>>(x, gate_w);                        // 2
    // 3: rank projections (dense K=2048 GEMM — profiling target)
    bgemm<0,1><<<dim3(32,1,4),256,GSMEM>>>(p_xs, H_, (size_t)T_*H_, 0,
        p_wproj, H_, 4*RH, RH, nullptr, p_projs, 4*TR, nullptr, R_, TR,
        T_, R_, H_, nullptr, nullptr, nullptr);
    scan_kernel<<<1,32>>>();                                   // 4
    compact_kernel<<<dim3(16,E_),256>>>();                     // 5

    // expert U (gather token rows)
    bgemm<0,0><<<dim3(32,1,E_),256,GSMEM>>>(p_projs + 0*TR, R_, 4*TR, 0,
        p_wUg, R_, (size_t)E_*RR, RR, nullptr, p_tgs, TKR, nullptr, R_, 0,
        0, R_, R_, p_off, p_map, nullptr);
    bgemm<0,0><<<dim3(32,1,E_),256,GSMEM>>>(p_projs + 1*TR, R_, 4*TR, 0,
        p_wUu, R_, (size_t)E_*RR, RR, nullptr, p_tus, TKR, nullptr, R_, 0,
        0, R_, R_, p_off, p_map, nullptr);
    // expert C-gate: silu -> fp32 hf
    bgemm<1,0><<<dim3(32,11,E_),256,GSMEM>>>(p_tgs, R_, TKR, 0,
        p_wCg, R_, (size_t)E_*I_*R_, (size_t)I_*R_, p_hf, nullptr, 0, nullptr, I_, 0,
        0, I_, R_, p_off, nullptr, nullptr);
    // expert C-up: (res * hf) -> h split
    bgemm<2,0><<<dim3(32,11,E_),256,GSMEM>>>(p_tus, R_, TKR, 0,
        p_wCu, R_, (size_t)E_*I_*R_, (size_t)I_*R_, nullptr, p_hs, TKI, p_hf, I_, 0,
        0, I_, R_, p_off, nullptr, nullptr);
    // Rd: [TK,1408] -> [TK,128]
    bgemm<0,1><<<dim3(128,1,1),256,GSMEM>>>(p_hs, I_, TKI, 0,
        p_wRd, I_, (size_t)R_*I_, 0, nullptr, p_rds, TKR, nullptr, R_, 0,
        TK_, R_, I_, nullptr, nullptr, nullptr);
    // expert Ud
    bgemm<0,0><<<dim3(32,1,E_),256,GSMEM>>>(p_rds, R_, TKR, 0,
        p_wUd, R_, (size_t)E_*RR, RR, nullptr, p_tds, TKR, nullptr, R_, 0,
        0, R_, R_, p_off, nullptr, nullptr);
    // expert Cd: rowscale -> eout fp32
    bgemm<3,0><<<dim3(32,16,E_),256,GSMEM>>>(p_tds, R_, TKR, 0,
        p_wCd, R_, (size_t)E_*H_*R_, (size_t)H_*R_, p_eout, nullptr, 0, nullptr, H_, 0,
        0, H_, R_, p_off, nullptr, p_ws);
    // shared U (z over gate/up)
    bgemm<0,1><<<dim3(32,1,2),256,GSMEM>>>(p_projs + 2*TR, R_, 4*TR, TR,
        p_wsU, R_, 2*RR, RR, nullptr, p_sts, 2*TR, nullptr, R_, TR,
        T_, R_, R_, nullptr, nullptr, nullptr);
    // shared C-gate: silu -> shf
    bgemm<1,1><<<dim3(32,22,1),256,GSMEM>>>(p_sts + 0*TR, R_, 2*TR, 0,
        p_wsCg, R_, SIR, 0, p_shf, nullptr, 0, nullptr, SI_, 0,
        T_, SI_, R_, nullptr, nullptr, nullptr);
    // shared C-up: (res * shf) -> sh split
    bgemm<2,1><<<dim3(32,22,1),256,GSMEM>>>(p_sts + 1*TR, R_, 2*TR, 0,
        p_wsCu, R_, SIR, 0, nullptr, p_shs, TSI, p_shf, SI_, 0,
        T_, SI_, R_, nullptr, nullptr, nullptr);
    // shared Rd: split-K=2 -> fp32 partials, reduce -> srd split
    bgemm<4,2><<<dim3(32,1,2),256,GSMEM>>>(p_shs, SI_, TSI, 0,
        p_wsRd, SI_, (size_t)R_*SI_, 0, p_skp, nullptr, 0, nullptr, R_, TR,
        T_, R_, SI_/2, nullptr, nullptr, nullptr);
    reduce_split_kernel<<<(T_*R_/2+255)/256,256>>>(p_skp, p_skp + TR, p_srds, p_srds + TR, T_*R_);
    // shared Ud
    bgemm<0,1><<<dim3(32,1,1),256,GSMEM>>>(p_srds, R_, TR, 0,
        p_wsUd, R_, RR, 0, nullptr, p_stds, TR, nullptr, R_, 0,
        T_, R_, R_, nullptr, nullptr, nullptr);
    // shared Cd + fused combine -> full d_out fp32 (EPI 5 gathers this token's 4 expert slots)
    bgemm<5,1><<<dim3(32,16,1),256,GSMEM>>>(p_stds, R_, TR, 0,
        p_wsCd, R_, (size_t)H_*R_, 0, out, nullptr, 0, nullptr, H_, 0,
        T_, H_, R_, nullptr, nullptr, nullptr);
}